// round 1
// baseline (speedup 1.0000x reference)
#include <cuda_runtime.h>
#include <cuda_bf16.h>
#include <math.h>

#define SEQ     4096
#define DMODEL  1024
#define DPROJ   4384
#define DINNER  2048
#define DCONVIN 2304
#define NH      32
#define HD      64
#define DS      128
#define CH      128
#define NC      32

// ---------------- scratch (device globals; no allocations allowed) ----------------
__device__ float g_zx[SEQ * DPROJ];         // in-proj output  [4096,4384]   71.8MB
__device__ float g_xBC[SEQ * DCONVIN];      // conv+silu out   [4096,2304]   37.7MB
__device__ float g_dt[SEQ * NH];            // softplus dt
__device__ float g_cs[NC * NH * CH];        // per-chunk cumsum of dt*A (log decay)
__device__ float g_cdecay[NC * NH];         // exp(cs[127]) per chunk/head
__device__ float g_CB[NC * CH * CH];        // C_t · B_s per chunk           2MB
__device__ float g_S[NC * NH * HD * DS];    // per-chunk local end-states    33.5MB
__device__ float g_h[NC * NH * HD * DS];    // prefix states (before chunk)  33.5MB
__device__ float g_y[SEQ * DINNER];         // y (pre-norm, then gated in-place)

__device__ __forceinline__ float bfr(float x) {
    return __bfloat162float(__float2bfloat16(x));
}
__device__ __forceinline__ float silu_f(float x) {
    return x / (1.f + expf(-x));
}

// ---------------- SGEMM: C[M,N] = A[M,K] @ B[N,K]^T (both K-contiguous) ----------------
template<bool ROUND_A>
__global__ void __launch_bounds__(256) sgemm_nt(
    const float* __restrict__ A, const float* __restrict__ B,
    float* __restrict__ C, int M, int N, int K)
{
    __shared__ float As[16][128];
    __shared__ float Bs[16][128];
    int tid = threadIdx.x;
    int tx = tid & 15, ty = tid >> 4;
    int m0 = blockIdx.y * 128, n0 = blockIdx.x * 128;
    float acc[8][8] = {};

    for (int k0 = 0; k0 < K; k0 += 16) {
        #pragma unroll
        for (int i = 0; i < 2; i++) {
            int l = tid + i * 256, r = l >> 2, c4 = (l & 3) * 4;
            float4 v = *(const float4*)(A + (size_t)(m0 + r) * K + k0 + c4);
            if (ROUND_A) { v.x = bfr(v.x); v.y = bfr(v.y); v.z = bfr(v.z); v.w = bfr(v.w); }
            As[c4 + 0][r] = v.x; As[c4 + 1][r] = v.y; As[c4 + 2][r] = v.z; As[c4 + 3][r] = v.w;
        }
        #pragma unroll
        for (int i = 0; i < 2; i++) {
            int l = tid + i * 256, r = l >> 2, c4 = (l & 3) * 4;
            int gn = n0 + r;
            float4 v = (gn < N) ? *(const float4*)(B + (size_t)gn * K + k0 + c4)
                                : make_float4(0.f, 0.f, 0.f, 0.f);
            Bs[c4 + 0][r] = v.x; Bs[c4 + 1][r] = v.y; Bs[c4 + 2][r] = v.z; Bs[c4 + 3][r] = v.w;
        }
        __syncthreads();
        #pragma unroll
        for (int k = 0; k < 16; k++) {
            float4 a0 = *(float4*)&As[k][ty * 8], a1 = *(float4*)&As[k][ty * 8 + 4];
            float4 b0 = *(float4*)&Bs[k][tx * 8], b1 = *(float4*)&Bs[k][tx * 8 + 4];
            float ra[8] = {a0.x, a0.y, a0.z, a0.w, a1.x, a1.y, a1.z, a1.w};
            float rb[8] = {b0.x, b0.y, b0.z, b0.w, b1.x, b1.y, b1.z, b1.w};
            #pragma unroll
            for (int i = 0; i < 8; i++)
                #pragma unroll
                for (int j = 0; j < 8; j++)
                    acc[i][j] += ra[i] * rb[j];
        }
        __syncthreads();
    }
    #pragma unroll
    for (int i = 0; i < 8; i++) {
        int m = m0 + ty * 8 + i;
        #pragma unroll
        for (int j = 0; j < 8; j++) {
            int n = n0 + tx * 8 + j;
            if (n < N) C[(size_t)m * N + n] = acc[i][j];
        }
    }
}

// ---------------- depthwise causal conv(4) + bias + SiLU ----------------
__global__ void conv_silu_kernel(const float* __restrict__ cw, const float* __restrict__ cb)
{
    int idx = blockIdx.x * blockDim.x + threadIdx.x;
    if (idx >= SEQ * DCONVIN) return;
    int t = idx / DCONVIN, c = idx % DCONVIN;
    float acc = cb[c];
    #pragma unroll
    for (int j = 0; j < 4; j++) {
        int tt = t - 3 + j;
        if (tt >= 0)
            acc += g_zx[(size_t)tt * DPROJ + 2048 + c] * cw[c * 4 + j];
    }
    g_xBC[idx] = silu_f(acc);
}

// ---------------- dt = softplus(raw + dt_bias) ----------------
__global__ void dt_kernel(const float* __restrict__ dtb)
{
    int idx = blockIdx.x * blockDim.x + threadIdx.x;
    if (idx >= SEQ * NH) return;
    int h = idx & 31;
    float raw = g_zx[(size_t)(idx >> 5) * DPROJ + 4352 + h] + dtb[h];
    g_dt[idx] = (raw > 20.f) ? raw : log1pf(expf(raw));
}

// ---------------- per-chunk cumsum of log-decay ----------------
__global__ void cumsum_kernel(const float* __restrict__ A_log)
{
    int c = blockIdx.x, h = threadIdx.x;
    float A = -expf(A_log[h]);
    float cs = 0.f;
    for (int t = 0; t < CH; t++) {
        cs += g_dt[(size_t)(c * CH + t) * NH + h] * A;
        g_cs[((size_t)c * NH + h) * CH + t] = cs;
    }
    g_cdecay[c * NH + h] = expf(cs);
}

// ---------------- CB[t][s] = C_t . B_s per chunk (head independent) ----------------
__global__ void __launch_bounds__(256) cb_kernel()
{
    int c = blockIdx.x, tid = threadIdx.x;
    __shared__ float Ct[128 * 33];
    __shared__ float Bt[128 * 33];
    int tx = tid & 15, ty = tid >> 4;
    int t0 = ty * 8, s0 = tx * 8;
    float acc[8][8] = {};
    for (int n0 = 0; n0 < DS; n0 += 32) {
        #pragma unroll
        for (int i = 0; i < 16; i++) {
            int l = tid + i * 256; int t = l >> 5, nn = l & 31;
            size_t base = (size_t)(c * CH + t) * DCONVIN;
            Ct[t * 33 + nn] = g_xBC[base + 2176 + n0 + nn];
            Bt[t * 33 + nn] = g_xBC[base + 2048 + n0 + nn];
        }
        __syncthreads();
        #pragma unroll
        for (int nn = 0; nn < 32; nn++) {
            float ra[8], rb[8];
            #pragma unroll
            for (int i = 0; i < 8; i++) ra[i] = Ct[(t0 + i) * 33 + nn];
            #pragma unroll
            for (int j = 0; j < 8; j++) rb[j] = Bt[(s0 + j) * 33 + nn];
            #pragma unroll
            for (int i = 0; i < 8; i++)
                #pragma unroll
                for (int j = 0; j < 8; j++)
                    acc[i][j] += ra[i] * rb[j];
        }
        __syncthreads();
    }
    #pragma unroll
    for (int i = 0; i < 8; i++)
        #pragma unroll
        for (int j = 0; j < 8; j++)
            g_CB[((size_t)c * CH + t0 + i) * CH + s0 + j] = acc[i][j];
}

// ---------------- per-chunk local end-state S[p,n] ----------------
__global__ void __launch_bounds__(256) s_kernel()
{
    int c = blockIdx.x, h = blockIdx.y, tid = threadIdx.x;
    __shared__ float xw[32 * 68];   // [ss][p], weighted x
    __shared__ float Bsh[32 * 132]; // [ss][n]
    __shared__ float wr[32];
    float csend = g_cs[((size_t)c * NH + h) * CH + 127];
    int tx = tid & 15, ty = tid >> 4;
    int nb = tx * 8, pb = ty * 4;
    float acc[4][8] = {};
    for (int s0 = 0; s0 < CH; s0 += 32) {
        if (tid < 32) {
            int s = s0 + tid;
            float cs_s = g_cs[((size_t)c * NH + h) * CH + s];
            wr[tid] = g_dt[(size_t)(c * CH + s) * NH + h] * expf(csend - cs_s);
        }
        __syncthreads();
        #pragma unroll
        for (int i = 0; i < 8; i++) {
            int l = tid + i * 256; int ss = l >> 6, p = l & 63;
            xw[ss * 68 + p] = wr[ss] * g_xBC[(size_t)(c * CH + s0 + ss) * DCONVIN + h * HD + p];
        }
        #pragma unroll
        for (int i = 0; i < 16; i++) {
            int l = tid + i * 256; int ss = l >> 7, n = l & 127;
            Bsh[ss * 132 + n] = g_xBC[(size_t)(c * CH + s0 + ss) * DCONVIN + 2048 + n];
        }
        __syncthreads();
        #pragma unroll
        for (int ss = 0; ss < 32; ss++) {
            float rx[4];
            #pragma unroll
            for (int i = 0; i < 4; i++) rx[i] = xw[ss * 68 + pb + i];
            float4 b0 = *(float4*)&Bsh[ss * 132 + nb], b1 = *(float4*)&Bsh[ss * 132 + nb + 4];
            float rb[8] = {b0.x, b0.y, b0.z, b0.w, b1.x, b1.y, b1.z, b1.w};
            #pragma unroll
            for (int i = 0; i < 4; i++)
                #pragma unroll
                for (int j = 0; j < 8; j++)
                    acc[i][j] += rx[i] * rb[j];
        }
        __syncthreads();
    }
    #pragma unroll
    for (int i = 0; i < 4; i++)
        #pragma unroll
        for (int j = 0; j < 8; j++)
            g_S[(((size_t)c * NH + h) * HD + pb + i) * DS + nb + j] = acc[i][j];
}

// ---------------- inter-chunk state scan (elementwise over (h,p,n)) ----------------
__global__ void scan_kernel()
{
    int idx = blockIdx.x * blockDim.x + threadIdx.x;
    if (idx >= NH * HD * DS) return;
    int h = idx / (HD * DS);
    float hs = 0.f;
    #pragma unroll 1
    for (int c = 0; c < NC; c++) {
        size_t o = (size_t)c * NH * HD * DS + idx;
        g_h[o] = hs;
        hs = hs * g_cdecay[c * NH + h] + g_S[o];
    }
}

// ---------------- y = intra + inter + D*x ----------------
__global__ void __launch_bounds__(256) y_kernel(const float* __restrict__ Dv)
{
    int c = blockIdx.x, h = blockIdx.y, tid = threadIdx.x;
    __shared__ float cs_sh[CH], dtr[CH], et[CH];
    __shared__ float bufA[32 * 133]; // phase A: M[t*33+ss] (128x33); phase B: C[nn*133+t]
    __shared__ float bufB[32 * 68];  // phase A: xdt[ss*68+p];       phase B: H[p*33+nn]
    if (tid < CH) {
        float cs = g_cs[((size_t)c * NH + h) * CH + tid];
        cs_sh[tid] = cs;
        et[tid] = expf(cs);
        dtr[tid] = g_dt[(size_t)(c * CH + tid) * NH + h];
    }
    __syncthreads();
    int ty = tid >> 3, tx = tid & 7;
    int tb = ty * 4, pb = tx * 8;
    float acc[4][8] = {}, iacc[4][8] = {};

    // ---- intra-chunk: y[t,p] += sum_{s<=t} CB[t,s]*exp(cs_t-cs_s) * (dt_s * x[s,p])
    for (int s0 = 0; s0 < CH; s0 += 32) {
        #pragma unroll
        for (int i = 0; i < 16; i++) {
            int l = tid + i * 256; int t = l >> 5, ss = l & 31, s = s0 + ss;
            float v = 0.f;
            if (s <= t)
                v = g_CB[((size_t)c * CH + t) * CH + s] * expf(cs_sh[t] - cs_sh[s]);
            bufA[t * 33 + ss] = v;
        }
        #pragma unroll
        for (int i = 0; i < 8; i++) {
            int l = tid + i * 256; int ss = l >> 6, p = l & 63, s = s0 + ss;
            bufB[ss * 68 + p] = dtr[s] * g_xBC[(size_t)(c * CH + s) * DCONVIN + h * HD + p];
        }
        __syncthreads();
        #pragma unroll
        for (int ss = 0; ss < 32; ss++) {
            float rm[4];
            #pragma unroll
            for (int i = 0; i < 4; i++) rm[i] = bufA[(tb + i) * 33 + ss];
            float4 x0 = *(float4*)&bufB[ss * 68 + pb], x1 = *(float4*)&bufB[ss * 68 + pb + 4];
            float rx[8] = {x0.x, x0.y, x0.z, x0.w, x1.x, x1.y, x1.z, x1.w};
            #pragma unroll
            for (int i = 0; i < 4; i++)
                #pragma unroll
                for (int j = 0; j < 8; j++)
                    acc[i][j] += rm[i] * rx[j];
        }
        __syncthreads();
    }

    // ---- inter-chunk: iacc[t,p] = sum_n C[t,n] * hprev[p,n]  (scaled by et[t] later)
    for (int n0 = 0; n0 < DS; n0 += 32) {
        #pragma unroll
        for (int i = 0; i < 16; i++) {
            int l = tid + i * 256; int t = l >> 5, nn = l & 31;
            bufA[nn * 133 + t] = g_xBC[(size_t)(c * CH + t) * DCONVIN + 2176 + n0 + nn];
        }
        #pragma unroll
        for (int i = 0; i < 8; i++) {
            int l = tid + i * 256; int p = l >> 5, nn = l & 31;
            bufB[p * 33 + nn] = g_h[(((size_t)c * NH + h) * HD + p) * DS + n0 + nn];
        }
        __syncthreads();
        #pragma unroll
        for (int nn = 0; nn < 32; nn++) {
            float rc[4], rh[8];
            #pragma unroll
            for (int i = 0; i < 4; i++) rc[i] = bufA[nn * 133 + tb + i];
            #pragma unroll
            for (int j = 0; j < 8; j++) rh[j] = bufB[(pb + j) * 33 + nn];
            #pragma unroll
            for (int i = 0; i < 4; i++)
                #pragma unroll
                for (int j = 0; j < 8; j++)
                    iacc[i][j] += rc[i] * rh[j];
        }
        __syncthreads();
    }

    float Dh = Dv[h];
    #pragma unroll
    for (int i = 0; i < 4; i++) {
        int t = tb + i; int row = c * CH + t;
        #pragma unroll
        for (int j = 0; j < 8; j++) {
            int p = pb + j;
            float x = g_xBC[(size_t)row * DCONVIN + h * HD + p];
            g_y[(size_t)row * DINNER + h * HD + p] = acc[i][j] + et[t] * iacc[i][j] + Dh * x;
        }
    }
}

// ---------------- RMSNorm + SiLU gate (in-place on g_y) ----------------
__global__ void __launch_bounds__(256) norm_gate_kernel(
    const float* __restrict__ nw, const float* __restrict__ nb)
{
    int t = blockIdx.x, tid = threadIdx.x;
    __shared__ float red[8];
    float ss = 0.f;
    for (int i = tid; i < DINNER; i += 256) {
        float v = g_y[(size_t)t * DINNER + i];
        ss += v * v;
    }
    #pragma unroll
    for (int o = 16; o > 0; o >>= 1) ss += __shfl_down_sync(0xffffffffu, ss, o);
    if ((tid & 31) == 0) red[tid >> 5] = ss;
    __syncthreads();
    if (tid < 8) {
        float v = red[tid];
        #pragma unroll
        for (int o = 4; o > 0; o >>= 1) v += __shfl_down_sync(0xffu, v, o);
        if (tid == 0) red[0] = v;
    }
    __syncthreads();
    float inv = rsqrtf(red[0] / (float)DINNER + 1e-6f);
    for (int i = tid; i < DINNER; i += 256) {
        float v = g_y[(size_t)t * DINNER + i] * inv * nw[i] + nb[i];
        float z = g_zx[(size_t)t * DPROJ + i];
        g_y[(size_t)t * DINNER + i] = v * silu_f(z);
    }
}

// ---------------- launch ----------------
extern "C" void kernel_launch(void* const* d_in, const int* in_sizes, int n_in,
                              void* d_out, int out_size)
{
    const float* u       = (const float*)d_in[0];
    const float* W_in    = (const float*)d_in[1];
    const float* conv_w  = (const float*)d_in[2];
    const float* conv_b  = (const float*)d_in[3];
    const float* W_out   = (const float*)d_in[4];
    const float* norm_w  = (const float*)d_in[5];
    const float* norm_b  = (const float*)d_in[6];
    const float* dt_bias = (const float*)d_in[7];
    const float* A_log   = (const float*)d_in[8];
    const float* Dv      = (const float*)d_in[9];
    float* out = (float*)d_out;

    float *zx_ptr = nullptr, *y_ptr = nullptr;
    cudaGetSymbolAddress((void**)&zx_ptr, g_zx);
    cudaGetSymbolAddress((void**)&y_ptr, g_y);

    // 1) zxbcdt = bf16(u) @ W_in^T
    sgemm_nt<true><<<dim3((DPROJ + 127) / 128, SEQ / 128), 256>>>(u, W_in, zx_ptr, SEQ, DPROJ, DMODEL);
    // 2) causal conv + SiLU
    conv_silu_kernel<<<(SEQ * DCONVIN + 255) / 256, 256>>>(conv_w, conv_b);
    // 3) dt, log-decay cumsums
    dt_kernel<<<(SEQ * NH + 255) / 256, 256>>>(dt_bias);
    cumsum_kernel<<<NC, NH>>>(A_log);
    // 4) per-chunk score matrix (head independent)
    cb_kernel<<<NC, 256>>>();
    // 5) per-chunk local end-states
    s_kernel<<<dim3(NC, NH), 256>>>();
    // 6) scan across chunks
    scan_kernel<<<(NH * HD * DS + 255) / 256, 256>>>();
    // 7) y = intra + inter + D*x
    y_kernel<<<dim3(NC, NH), 256>>>(Dv);
    // 8) RMSNorm + gate
    norm_gate_kernel<<<SEQ, 256>>>(norm_w, norm_b);
    // 9) out = y @ W_out^T
    sgemm_nt<false><<<dim3((DMODEL + 127) / 128, SEQ / 128), 256>>>(y_ptr, W_out, out, SEQ, DMODEL, DINNER);
}

// round 4
// speedup vs baseline: 1.8130x; 1.8130x over previous
#include <cuda_runtime.h>
#include <cuda_bf16.h>
#include <cuda_pipeline.h>
#include <mma.h>
#include <math.h>

using namespace nvcuda;

#define SEQ     4096
#define DMODEL  1024
#define DPROJ   4384
#define DINNER  2048
#define DCONVIN 2304
#define NH      32
#define HD      64
#define DS      128
#define CH      128
#define NC      32

// ---------------- scratch (device globals; no allocations allowed) ----------------
__device__ float g_zx[SEQ * DPROJ];
__device__ float g_xBC[SEQ * DCONVIN];
__device__ float g_dt[SEQ * NH];
__device__ float g_cs[NC * NH * CH];
__device__ float g_cdecay[NC * NH];
__device__ float g_CB[NC * CH * CH];
__device__ float g_S[NC * NH * HD * DS];
__device__ float g_h[NC * NH * HD * DS];
__device__ float g_y[SEQ * DINNER];

__device__ __nv_bfloat16 g_ubf[SEQ * DMODEL];
__device__ __nv_bfloat16 g_wih[DPROJ * DMODEL];
__device__ __nv_bfloat16 g_wil[DPROJ * DMODEL];
__device__ __nv_bfloat16 g_woh[DMODEL * DINNER];
__device__ __nv_bfloat16 g_wol[DMODEL * DINNER];
__device__ __nv_bfloat16 g_yh[SEQ * DINNER];
__device__ __nv_bfloat16 g_yl[SEQ * DINNER];

__device__ __forceinline__ float silu_f(float x) {
    return x / (1.f + expf(-x));
}

// ---------------- conversion kernels ----------------
__global__ void to_bf16_kernel(const float* __restrict__ src, __nv_bfloat16* __restrict__ dst, int n) {
    int i = blockIdx.x * blockDim.x + threadIdx.x;
    if (i < n) dst[i] = __float2bfloat16(src[i]);
}
__global__ void split_bf16_kernel(const float* __restrict__ src,
                                  __nv_bfloat16* __restrict__ hi, __nv_bfloat16* __restrict__ lo, int n) {
    int i = blockIdx.x * blockDim.x + threadIdx.x;
    if (i < n) {
        float x = src[i];
        __nv_bfloat16 h = __float2bfloat16(x);
        hi[i] = h;
        lo[i] = __float2bfloat16(x - __bfloat162float(h));
    }
}

// ---------------- bf16 wmma GEMM with hi/lo split ----------------
// C[M,N] = A0*B0 + A0*B1 (+ A1*B0 if NA==2).  A rows: [M][K], B rows: [N][K].
template<int NA>
__device__ __forceinline__ void gemm_body(
    const __nv_bfloat16* __restrict__ A0, const __nv_bfloat16* __restrict__ A1,
    const __nv_bfloat16* __restrict__ B0, const __nv_bfloat16* __restrict__ B1,
    float* __restrict__ C, int M, int N, int K)
{
    extern __shared__ __align__(128) __nv_bfloat16 sm[];
    const int LD = 48;                 // halves per smem row (96B, 32B-multiple)
    const int MATSZ = 128 * LD;
    const int NMAT = NA + 2;
    const int STAGE = NMAT * MATSZ;

    const int tid = threadIdx.x;
    const int warp = tid >> 5;
    const int wm = warp >> 2, wn = warp & 3;       // 2x4 warp grid; warp tile 64x32
    const int m0 = blockIdx.y * 128, n0 = blockIdx.x * 128;

    const int crow = tid >> 2;                     // 64 rows per copy pass
    const int ccol = (tid & 3) * 8;                // 8 halves = 16B

    const __nv_bfloat16* Asrc[2];
    Asrc[0] = A0; Asrc[1] = A1;
    const __nv_bfloat16* Bsrc[2];
    Bsrc[0] = B0; Bsrc[1] = B1;

    wmma::fragment<wmma::accumulator, 16, 16, 16, float> fc[4][2];
    for (int i = 0; i < 4; i++)
        for (int j = 0; j < 2; j++)
            wmma::fill_fragment(fc[i][j], 0.f);

    const int nk = K / 32;

    // prologue: stage 0
    for (int v = 0; v < NA; v++)
        for (int p = 0; p < 2; p++) {
            int r = crow + p * 64;
            __pipeline_memcpy_async(sm + v * MATSZ + r * LD + ccol,
                                    Asrc[v] + (size_t)(m0 + r) * K + ccol, 16);
        }
    for (int v = 0; v < 2; v++)
        for (int p = 0; p < 2; p++) {
            int r = crow + p * 64;
            int gn = n0 + r; if (gn >= N) gn = N - 1;
            __pipeline_memcpy_async(sm + (NA + v) * MATSZ + r * LD + ccol,
                                    Bsrc[v] + (size_t)gn * K + ccol, 16);
        }
    __pipeline_commit();

    for (int kt = 0; kt < nk; kt++) {
        __pipeline_wait_prior(0);
        __syncthreads();
        if (kt + 1 < nk) {
            const int k0 = (kt + 1) * 32;
            __nv_bfloat16* sb = sm + ((kt + 1) & 1) * STAGE;
            for (int v = 0; v < NA; v++)
                for (int p = 0; p < 2; p++) {
                    int r = crow + p * 64;
                    __pipeline_memcpy_async(sb + v * MATSZ + r * LD + ccol,
                                            Asrc[v] + (size_t)(m0 + r) * K + k0 + ccol, 16);
                }
            for (int v = 0; v < 2; v++)
                for (int p = 0; p < 2; p++) {
                    int r = crow + p * 64;
                    int gn = n0 + r; if (gn >= N) gn = N - 1;
                    __pipeline_memcpy_async(sb + (NA + v) * MATSZ + r * LD + ccol,
                                            Bsrc[v] + (size_t)gn * K + k0 + ccol, 16);
                }
            __pipeline_commit();
        }

        const __nv_bfloat16* sbase = sm + (kt & 1) * STAGE;
        #pragma unroll
        for (int kk = 0; kk < 32; kk += 16) {
            wmma::fragment<wmma::matrix_b, 16, 16, 16, __nv_bfloat16, wmma::col_major> fb[2][2];
            #pragma unroll
            for (int v = 0; v < 2; v++)
                #pragma unroll
                for (int ni = 0; ni < 2; ni++)
                    wmma::load_matrix_sync(fb[v][ni],
                        sbase + (NA + v) * MATSZ + (wn * 32 + ni * 16) * LD + kk, LD);
            #pragma unroll
            for (int mi = 0; mi < 4; mi++) {
                wmma::fragment<wmma::matrix_a, 16, 16, 16, __nv_bfloat16, wmma::row_major> fa0;
                wmma::load_matrix_sync(fa0, sbase + (wm * 64 + mi * 16) * LD + kk, LD);
                #pragma unroll
                for (int ni = 0; ni < 2; ni++) {
                    wmma::mma_sync(fc[mi][ni], fa0, fb[0][ni], fc[mi][ni]);
                    wmma::mma_sync(fc[mi][ni], fa0, fb[1][ni], fc[mi][ni]);
                }
                if (NA == 2) {
                    wmma::fragment<wmma::matrix_a, 16, 16, 16, __nv_bfloat16, wmma::row_major> fa1;
                    wmma::load_matrix_sync(fa1, sbase + MATSZ + (wm * 64 + mi * 16) * LD + kk, LD);
                    #pragma unroll
                    for (int ni = 0; ni < 2; ni++)
                        wmma::mma_sync(fc[mi][ni], fa1, fb[0][ni], fc[mi][ni]);
                }
            }
        }
        __syncthreads();
    }

    for (int mi = 0; mi < 4; mi++)
        for (int ni = 0; ni < 2; ni++) {
            int m = m0 + wm * 64 + mi * 16;
            int n = n0 + wn * 32 + ni * 16;
            if (n + 16 <= N)
                wmma::store_matrix_sync(C + (size_t)m * N + n, fc[mi][ni], N, wmma::mem_row_major);
        }
}

__global__ void __launch_bounds__(256) gemm_na1(
    const __nv_bfloat16* __restrict__ A0,
    const __nv_bfloat16* __restrict__ B0, const __nv_bfloat16* __restrict__ B1,
    float* __restrict__ C, int M, int N, int K)
{
    gemm_body<1>(A0, A0, B0, B1, C, M, N, K);
}
__global__ void __launch_bounds__(256) gemm_na2(
    const __nv_bfloat16* __restrict__ A0, const __nv_bfloat16* __restrict__ A1,
    const __nv_bfloat16* __restrict__ B0, const __nv_bfloat16* __restrict__ B1,
    float* __restrict__ C, int M, int N, int K)
{
    gemm_body<2>(A0, A1, B0, B1, C, M, N, K);
}

// ---------------- depthwise causal conv(4) + bias + SiLU ----------------
__global__ void conv_silu_kernel(const float* __restrict__ cw, const float* __restrict__ cb)
{
    int idx = blockIdx.x * blockDim.x + threadIdx.x;
    if (idx >= SEQ * DCONVIN) return;
    int t = idx / DCONVIN, c = idx % DCONVIN;
    float acc = cb[c];
    #pragma unroll
    for (int j = 0; j < 4; j++) {
        int tt = t - 3 + j;
        if (tt >= 0)
            acc += g_zx[(size_t)tt * DPROJ + 2048 + c] * cw[c * 4 + j];
    }
    g_xBC[idx] = silu_f(acc);
}

// ---------------- fused softplus dt + per-chunk cumsum (warp per (c,h)) ----------------
__global__ void __launch_bounds__(256) cumsum_kernel(const float* __restrict__ A_log,
                                                     const float* __restrict__ dtb)
{
    int c = blockIdx.x;
    int h = blockIdx.y * 8 + (threadIdx.x >> 5);
    int lane = threadIdx.x & 31;
    float A = -expf(A_log[h]);
    float b = dtb[h];
    float d[4], s = 0.f;
    #pragma unroll
    for (int j = 0; j < 4; j++) {
        int t = lane * 4 + j;
        float raw = g_zx[(size_t)(c * CH + t) * DPROJ + 4352 + h] + b;
        float dt = (raw > 20.f) ? raw : log1pf(expf(raw));
        g_dt[(size_t)(c * CH + t) * NH + h] = dt;
        d[j] = dt * A;
        s += d[j];
    }
    float ex = s;
    #pragma unroll
    for (int o = 1; o < 32; o <<= 1) {
        float v = __shfl_up_sync(0xffffffffu, ex, o);
        if (lane >= o) ex += v;
    }
    ex -= s;
    float cs = ex;
    #pragma unroll
    for (int j = 0; j < 4; j++) {
        cs += d[j];
        g_cs[((size_t)c * NH + h) * CH + lane * 4 + j] = cs;
    }
    if (lane == 31) g_cdecay[c * NH + h] = expf(cs);
}

// ---------------- CB[t][s] = C_t . B_s per chunk ----------------
__global__ void __launch_bounds__(256) cb_kernel()
{
    int c = blockIdx.x, tid = threadIdx.x;
    __shared__ float Ct[128 * 33];
    __shared__ float Bt[128 * 33];
    int tx = tid & 15, ty = tid >> 4;
    int t0 = ty * 8, s0 = tx * 8;
    float acc[8][8] = {};
    for (int n0 = 0; n0 < DS; n0 += 32) {
        #pragma unroll
        for (int i = 0; i < 16; i++) {
            int l = tid + i * 256; int t = l >> 5, nn = l & 31;
            size_t base = (size_t)(c * CH + t) * DCONVIN;
            Ct[t * 33 + nn] = g_xBC[base + 2176 + n0 + nn];
            Bt[t * 33 + nn] = g_xBC[base + 2048 + n0 + nn];
        }
        __syncthreads();
        #pragma unroll
        for (int nn = 0; nn < 32; nn++) {
            float ra[8], rb[8];
            #pragma unroll
            for (int i = 0; i < 8; i++) ra[i] = Ct[(t0 + i) * 33 + nn];
            #pragma unroll
            for (int j = 0; j < 8; j++) rb[j] = Bt[(s0 + j) * 33 + nn];
            #pragma unroll
            for (int i = 0; i < 8; i++)
                #pragma unroll
                for (int j = 0; j < 8; j++)
                    acc[i][j] += ra[i] * rb[j];
        }
        __syncthreads();
    }
    #pragma unroll
    for (int i = 0; i < 8; i++)
        #pragma unroll
        for (int j = 0; j < 8; j++)
            g_CB[((size_t)c * CH + t0 + i) * CH + s0 + j] = acc[i][j];
}

// ---------------- per-chunk local end-state S[p,n] ----------------
__global__ void __launch_bounds__(256) s_kernel()
{
    int c = blockIdx.x, h = blockIdx.y, tid = threadIdx.x;
    __shared__ float xw[32 * 68];
    __shared__ float Bsh[32 * 132];
    __shared__ float wr[32];
    float csend = g_cs[((size_t)c * NH + h) * CH + 127];
    int tx = tid & 15, ty = tid >> 4;
    int nb = tx * 8, pb = ty * 4;
    float acc[4][8] = {};
    for (int s0 = 0; s0 < CH; s0 += 32) {
        if (tid < 32) {
            int s = s0 + tid;
            float cs_s = g_cs[((size_t)c * NH + h) * CH + s];
            wr[tid] = g_dt[(size_t)(c * CH + s) * NH + h] * expf(csend - cs_s);
        }
        __syncthreads();
        #pragma unroll
        for (int i = 0; i < 8; i++) {
            int l = tid + i * 256; int ss = l >> 6, p = l & 63;
            xw[ss * 68 + p] = wr[ss] * g_xBC[(size_t)(c * CH + s0 + ss) * DCONVIN + h * HD + p];
        }
        #pragma unroll
        for (int i = 0; i < 16; i++) {
            int l = tid + i * 256; int ss = l >> 7, n = l & 127;
            Bsh[ss * 132 + n] = g_xBC[(size_t)(c * CH + s0 + ss) * DCONVIN + 2048 + n];
        }
        __syncthreads();
        #pragma unroll
        for (int ss = 0; ss < 32; ss++) {
            float rx[4];
            #pragma unroll
            for (int i = 0; i < 4; i++) rx[i] = xw[ss * 68 + pb + i];
            float4 b0 = *(float4*)&Bsh[ss * 132 + nb], b1 = *(float4*)&Bsh[ss * 132 + nb + 4];
            float rb[8] = {b0.x, b0.y, b0.z, b0.w, b1.x, b1.y, b1.z, b1.w};
            #pragma unroll
            for (int i = 0; i < 4; i++)
                #pragma unroll
                for (int j = 0; j < 8; j++)
                    acc[i][j] += rx[i] * rb[j];
        }
        __syncthreads();
    }
    #pragma unroll
    for (int i = 0; i < 4; i++)
        #pragma unroll
        for (int j = 0; j < 8; j++)
            g_S[(((size_t)c * NH + h) * HD + pb + i) * DS + nb + j] = acc[i][j];
}

// ---------------- inter-chunk state scan ----------------
__global__ void scan_kernel()
{
    int idx = blockIdx.x * blockDim.x + threadIdx.x;
    if (idx >= NH * HD * DS) return;
    int h = idx / (HD * DS);
    float hs = 0.f;
    #pragma unroll 1
    for (int c = 0; c < NC; c++) {
        size_t o = (size_t)c * NH * HD * DS + idx;
        g_h[o] = hs;
        hs = hs * g_cdecay[c * NH + h] + g_S[o];
    }
}

// ---------------- y = intra + inter + D*x ----------------
__global__ void __launch_bounds__(256) y_kernel(const float* __restrict__ Dv)
{
    int c = blockIdx.x, h = blockIdx.y, tid = threadIdx.x;
    __shared__ float cs_sh[CH], dtr[CH], et[CH];
    __shared__ float bufA[32 * 133];
    __shared__ float bufB[32 * 68];
    if (tid < CH) {
        float cs = g_cs[((size_t)c * NH + h) * CH + tid];
        cs_sh[tid] = cs;
        et[tid] = expf(cs);
        dtr[tid] = g_dt[(size_t)(c * CH + tid) * NH + h];
    }
    __syncthreads();
    int ty = tid >> 3, tx = tid & 7;
    int tb = ty * 4, pb = tx * 8;
    float acc[4][8] = {}, iacc[4][8] = {};

    for (int s0 = 0; s0 < CH; s0 += 32) {
        #pragma unroll
        for (int i = 0; i < 16; i++) {
            int l = tid + i * 256; int t = l >> 5, ss = l & 31, s = s0 + ss;
            float v = 0.f;
            if (s <= t)
                v = g_CB[((size_t)c * CH + t) * CH + s] * expf(cs_sh[t] - cs_sh[s]);
            bufA[t * 33 + ss] = v;
        }
        #pragma unroll
        for (int i = 0; i < 8; i++) {
            int l = tid + i * 256; int ss = l >> 6, p = l & 63, s = s0 + ss;
            bufB[ss * 68 + p] = dtr[s] * g_xBC[(size_t)(c * CH + s) * DCONVIN + h * HD + p];
        }
        __syncthreads();
        #pragma unroll
        for (int ss = 0; ss < 32; ss++) {
            float rm[4];
            #pragma unroll
            for (int i = 0; i < 4; i++) rm[i] = bufA[(tb + i) * 33 + ss];
            float4 x0 = *(float4*)&bufB[ss * 68 + pb], x1 = *(float4*)&bufB[ss * 68 + pb + 4];
            float rx[8] = {x0.x, x0.y, x0.z, x0.w, x1.x, x1.y, x1.z, x1.w};
            #pragma unroll
            for (int i = 0; i < 4; i++)
                #pragma unroll
                for (int j = 0; j < 8; j++)
                    acc[i][j] += rm[i] * rx[j];
        }
        __syncthreads();
    }

    for (int n0 = 0; n0 < DS; n0 += 32) {
        #pragma unroll
        for (int i = 0; i < 16; i++) {
            int l = tid + i * 256; int t = l >> 5, nn = l & 31;
            bufA[nn * 133 + t] = g_xBC[(size_t)(c * CH + t) * DCONVIN + 2176 + n0 + nn];
        }
        #pragma unroll
        for (int i = 0; i < 8; i++) {
            int l = tid + i * 256; int p = l >> 5, nn = l & 31;
            bufB[p * 33 + nn] = g_h[(((size_t)c * NH + h) * HD + p) * DS + n0 + nn];
        }
        __syncthreads();
        #pragma unroll
        for (int nn = 0; nn < 32; nn++) {
            float rc[4], rh[8];
            #pragma unroll
            for (int i = 0; i < 4; i++) rc[i] = bufA[nn * 133 + tb + i];
            #pragma unroll
            for (int j = 0; j < 8; j++) rh[j] = bufB[(pb + j) * 33 + nn];
            #pragma unroll
            for (int i = 0; i < 4; i++)
                #pragma unroll
                for (int j = 0; j < 8; j++)
                    iacc[i][j] += rc[i] * rh[j];
        }
        __syncthreads();
    }

    float Dh = Dv[h];
    #pragma unroll
    for (int i = 0; i < 4; i++) {
        int t = tb + i; int row = c * CH + t;
        #pragma unroll
        for (int j = 0; j < 8; j++) {
            int p = pb + j;
            float x = g_xBC[(size_t)row * DCONVIN + h * HD + p];
            g_y[(size_t)row * DINNER + h * HD + p] = acc[i][j] + et[t] * iacc[i][j] + Dh * x;
        }
    }
}

// ---------------- RMSNorm + SiLU gate -> bf16 hi/lo ----------------
__global__ void __launch_bounds__(256) norm_gate_kernel(
    const float* __restrict__ nw, const float* __restrict__ nb)
{
    int t = blockIdx.x, tid = threadIdx.x;
    __shared__ float red[8];
    float ss = 0.f;
    for (int i = tid; i < DINNER; i += 256) {
        float v = g_y[(size_t)t * DINNER + i];
        ss += v * v;
    }
    #pragma unroll
    for (int o = 16; o > 0; o >>= 1) ss += __shfl_down_sync(0xffffffffu, ss, o);
    if ((tid & 31) == 0) red[tid >> 5] = ss;
    __syncthreads();
    if (tid < 8) {
        float v = red[tid];
        #pragma unroll
        for (int o = 4; o > 0; o >>= 1) v += __shfl_down_sync(0xffu, v, o);
        if (tid == 0) red[0] = v;
    }
    __syncthreads();
    float inv = rsqrtf(red[0] / (float)DINNER + 1e-6f);
    for (int i = tid; i < DINNER; i += 256) {
        float v = g_y[(size_t)t * DINNER + i] * inv * nw[i] + nb[i];
        float z = g_zx[(size_t)t * DPROJ + i];
        float gv = v * silu_f(z);
        __nv_bfloat16 hv = __float2bfloat16(gv);
        g_yh[(size_t)t * DINNER + i] = hv;
        g_yl[(size_t)t * DINNER + i] = __float2bfloat16(gv - __bfloat162float(hv));
    }
}

// ---------------- launch ----------------
extern "C" void kernel_launch(void* const* d_in, const int* in_sizes, int n_in,
                              void* d_out, int out_size)
{
    const float* u       = (const float*)d_in[0];
    const float* W_in    = (const float*)d_in[1];
    const float* conv_w  = (const float*)d_in[2];
    const float* conv_b  = (const float*)d_in[3];
    const float* W_out   = (const float*)d_in[4];
    const float* norm_w  = (const float*)d_in[5];
    const float* norm_b  = (const float*)d_in[6];
    const float* dt_bias = (const float*)d_in[7];
    const float* A_log   = (const float*)d_in[8];
    const float* Dv      = (const float*)d_in[9];
    float* out = (float*)d_out;

    float* zx_ptr = 0;
    __nv_bfloat16 *ubf, *wih, *wil, *woh, *wol, *yh, *yl;
    cudaGetSymbolAddress((void**)&zx_ptr, g_zx);
    cudaGetSymbolAddress((void**)&ubf, g_ubf);
    cudaGetSymbolAddress((void**)&wih, g_wih);
    cudaGetSymbolAddress((void**)&wil, g_wil);
    cudaGetSymbolAddress((void**)&woh, g_woh);
    cudaGetSymbolAddress((void**)&wol, g_wol);
    cudaGetSymbolAddress((void**)&yh, g_yh);
    cudaGetSymbolAddress((void**)&yl, g_yl);

    const int smem1 = 3 * 128 * 48 * 2 * 2;   // 73728 B
    const int smem2 = 4 * 128 * 48 * 2 * 2;   // 98304 B
    cudaFuncSetAttribute(gemm_na1, cudaFuncAttributeMaxDynamicSharedMemorySize, smem1);
    cudaFuncSetAttribute(gemm_na2, cudaFuncAttributeMaxDynamicSharedMemorySize, smem2);

    // 0) precision staging
    to_bf16_kernel<<<(SEQ * DMODEL + 255) / 256, 256>>>(u, ubf, SEQ * DMODEL);
    split_bf16_kernel<<<(DPROJ * DMODEL + 255) / 256, 256>>>(W_in, wih, wil, DPROJ * DMODEL);
    split_bf16_kernel<<<(DMODEL * DINNER + 255) / 256, 256>>>(W_out, woh, wol, DMODEL * DINNER);

    // 1) zxbcdt = bf16(u) @ W_in^T
    gemm_na1<<<dim3((DPROJ + 127) / 128, SEQ / 128), 256, smem1>>>(
        ubf, wih, wil, zx_ptr, SEQ, DPROJ, DMODEL);
    // 2) causal conv + SiLU
    conv_silu_kernel<<<(SEQ * DCONVIN + 255) / 256, 256>>>(conv_w, conv_b);
    // 3) dt + log-decay cumsums (fused)
    cumsum_kernel<<<dim3(NC, 4), 256>>>(A_log, dt_bias);
    // 4) per-chunk score matrix
    cb_kernel<<<NC, 256>>>();
    // 5) per-chunk local end-states
    s_kernel<<<dim3(NC, NH), 256>>>();
    // 6) scan across chunks
    scan_kernel<<<(NH * HD * DS + 255) / 256, 256>>>();
    // 7) y = intra + inter + D*x
    y_kernel<<<dim3(NC, NH), 256>>>(Dv);
    // 8) RMSNorm + gate -> bf16 hi/lo
    norm_gate_kernel<<<SEQ, 256>>>(norm_w, norm_b);
    // 9) out = y @ W_out^T
    gemm_na2<<<dim3(DMODEL / 128, SEQ / 128), 256, smem2>>>(
        yh, yl, woh, wol, out, SEQ, DMODEL, DINNER);
}